// round 2
// baseline (speedup 1.0000x reference)
#include <cuda_runtime.h>

#define BB 256
#define TT 512
#define KK 128

// ---- scratch (no allocations allowed) ----
__device__ unsigned char g_bp[(long)BB * TT * KK];   // backpointers (bytes)
__device__ float g_vfin[BB * KK];                    // final viterbi scores
__device__ float g_lognorm[BB];                      // log partition per batch
__device__ float g_ll[BB];                           // log-likelihood per batch
__device__ int   g_correct[BB];
__device__ int   g_total[BB];

// ============================================================
// Kernel 1: fused scans. Blocks [0,256) = Viterbi forward,
// blocks [256,512) = CRF forward (exp-domain logsumexp).
// One thread per destination tag k; transition column in registers.
// ============================================================
__global__ __launch_bounds__(128)
void crf_scan_kernel(const float* __restrict__ emissions,
                     const int*   __restrict__ lengths,
                     const float* __restrict__ trans)
{
    __shared__ float4 bufS[2][KK / 4];   // state vector (double buffer)
    __shared__ float  redS[4];

    const int k    = threadIdx.x;
    const int role = (blockIdx.x >= BB);
    const int b    = role ? (blockIdx.x - BB) : blockIdx.x;
    const int len  = lengths[b];
    const float* em = emissions + (long)b * TT * KK;

    if (!role) {
        // -------- Viterbi forward --------
        float treg[KK];
        #pragma unroll
        for (int j = 0; j < KK; j++) treg[j] = trans[j * KK + k];  // column k

        float v = em[k];                       // t = 0
        int buf = 0;
        ((float*)bufS[0])[k] = v;
        __syncthreads();

        unsigned char* bp = g_bp + (long)b * TT * KK;

        float emit = em[KK + k];               // prefetch t = 1
        for (int t = 1; t < TT; t++) {
            float emit_next = (t + 1 < TT) ? em[(t + 1) * KK + k] : 0.0f;

            float best = -3.4e38f;
            int   bi   = 0;
            #pragma unroll
            for (int jj = 0; jj < KK / 4; jj++) {
                float4 q = bufS[buf][jj];
                float w;
                w = q.x + treg[4*jj+0]; if (w > best) { best = w; bi = 4*jj+0; }
                w = q.y + treg[4*jj+1]; if (w > best) { best = w; bi = 4*jj+1; }
                w = q.z + treg[4*jj+2]; if (w > best) { best = w; bi = 4*jj+2; }
                w = q.w + treg[4*jj+3]; if (w > best) { best = w; bi = 4*jj+3; }
            }
            bool valid = (t < len);
            if (valid) v = best + emit;
            bp[t * KK + k] = valid ? (unsigned char)bi : (unsigned char)k;

            ((float*)bufS[buf ^ 1])[k] = v;
            __syncthreads();
            buf ^= 1;
            emit = emit_next;
        }
        g_vfin[b * KK + k] = v;
    } else {
        // -------- CRF forward (log partition), exp-domain --------
        float Ereg[KK];
        #pragma unroll
        for (int j = 0; j < KK; j++) Ereg[j] = __expf(trans[j * KK + k]);

        float alpha = em[k];
        const int wid = k >> 5, lane = k & 31;

        float emit = em[KK + k];
        for (int t = 1; t < TT; t++) {
            float emit_next = (t + 1 < TT) ? em[(t + 1) * KK + k] : 0.0f;

            // block max of alpha
            float mw = alpha;
            #pragma unroll
            for (int o = 16; o > 0; o >>= 1)
                mw = fmaxf(mw, __shfl_xor_sync(0xffffffffu, mw, o));
            if (lane == 0) redS[wid] = mw;
            __syncthreads();
            float m = fmaxf(fmaxf(redS[0], redS[1]), fmaxf(redS[2], redS[3]));

            float p = __expf(alpha - m);
            ((float*)bufS[0])[k] = p;
            __syncthreads();

            float s0 = 0.f, s1 = 0.f, s2 = 0.f, s3 = 0.f;
            #pragma unroll
            for (int jj = 0; jj < KK / 4; jj++) {
                float4 q = bufS[0][jj];
                s0 = fmaf(q.x, Ereg[4*jj+0], s0);
                s1 = fmaf(q.y, Ereg[4*jj+1], s1);
                s2 = fmaf(q.z, Ereg[4*jj+2], s2);
                s3 = fmaf(q.w, Ereg[4*jj+3], s3);
            }
            float s = (s0 + s1) + (s2 + s3);
            if (t < len) alpha = m + __logf(s) + emit;
            emit = emit_next;
        }

        // final logsumexp over k
        float mw = alpha;
        #pragma unroll
        for (int o = 16; o > 0; o >>= 1)
            mw = fmaxf(mw, __shfl_xor_sync(0xffffffffu, mw, o));
        if (lane == 0) redS[wid] = mw;
        __syncthreads();
        float m = fmaxf(fmaxf(redS[0], redS[1]), fmaxf(redS[2], redS[3]));
        float p = __expf(alpha - m);
        #pragma unroll
        for (int o = 16; o > 0; o >>= 1)
            p += __shfl_xor_sync(0xffffffffu, p, o);
        __syncthreads();
        if (lane == 0) redS[wid] = p;
        __syncthreads();
        if (k == 0) {
            float s = redS[0] + redS[1] + redS[2] + redS[3];
            g_lognorm[b] = m + __logf(s);
        }
    }
}

// ============================================================
// Kernel 2: backtrack + gold score + accuracy counts.
// One block per batch element.
// ============================================================
__global__ __launch_bounds__(128)
void crf_backtrack_kernel(const float* __restrict__ emissions,
                          const int*   __restrict__ tag_ids,
                          const int*   __restrict__ lengths,
                          const float* __restrict__ trans,
                          float*       __restrict__ out)
{
    __shared__ unsigned int rowS[64 * KK / 4];   // 8KB: 64 bp rows
    __shared__ int   tagS[TT];
    __shared__ float fredS[4];
    __shared__ int   iredS[4];

    const int b = blockIdx.x, k = threadIdx.x;
    const int wid = k >> 5, lane = k & 31;

    // ---- last_tag = argmax(v_final), first index on ties ----
    float v = g_vfin[b * KK + k];
    int   idx = k;
    #pragma unroll
    for (int o = 16; o > 0; o >>= 1) {
        float ov = __shfl_xor_sync(0xffffffffu, v, o);
        int   oi = __shfl_xor_sync(0xffffffffu, idx, o);
        if (ov > v || (ov == v && oi < idx)) { v = ov; idx = oi; }
    }
    if (lane == 0) { fredS[wid] = v; iredS[wid] = idx; }
    __syncthreads();
    if (k == 0) {
        float bv = fredS[0]; int bi = iredS[0];
        for (int w = 1; w < 4; w++)
            if (fredS[w] > bv || (fredS[w] == bv && iredS[w] < bi)) { bv = fredS[w]; bi = iredS[w]; }
        tagS[TT - 1] = bi;
    }
    __syncthreads();

    // ---- chunked backward walk through backpointers ----
    int cur = tagS[TT - 1];   // only thread 0's copy matters
    const unsigned int* bpu = (const unsigned int*)g_bp + (long)b * TT * KK / 4;
    for (int c = 0; c < 8; c++) {
        int hi = TT - 1 - c * 64;
        int lo = hi - 63;
        const unsigned int* src = bpu + lo * (KK / 4);
        for (int i = k; i < 64 * KK / 4; i += 128) rowS[i] = src[i];
        __syncthreads();
        if (k == 0) {
            const unsigned char* rb = (const unsigned char*)rowS;
            int tmin = (lo > 1) ? lo : 1;
            for (int t = hi; t >= tmin; t--) {
                cur = rb[(t - lo) * KK + cur];
                tagS[t - 1] = cur;
            }
        }
        __syncthreads();
    }

    // ---- decoded output + gold-path score + accuracy ----
    const int len = lengths[b];
    float sc = 0.f;
    int correct = 0;
    for (int t = k; t < TT; t += 128) {
        int tg = tagS[t];
        out[1 + b * TT + t] = (float)tg;
        int ref = tag_ids[b * TT + t];
        if (t < len) {
            correct += (ref == tg);
            sc += emissions[((long)b * TT + t) * KK + ref];
            if (t >= 1) sc += trans[tag_ids[b * TT + t - 1] * KK + ref];
        }
    }
    #pragma unroll
    for (int o = 16; o > 0; o >>= 1) {
        sc      += __shfl_xor_sync(0xffffffffu, sc, o);
        correct += __shfl_xor_sync(0xffffffffu, correct, o);
    }
    if (lane == 0) { fredS[wid] = sc; iredS[wid] = correct; }
    __syncthreads();
    if (k == 0) {
        float S = fredS[0] + fredS[1] + fredS[2] + fredS[3];
        int   C = iredS[0] + iredS[1] + iredS[2] + iredS[3];
        g_ll[b] = S - g_lognorm[b];
        g_correct[b] = C;
        g_total[b] = len;
    }
}

// ============================================================
// Kernel 3: finalize loss + accuracy (deterministic).
// ============================================================
__global__ void crf_finalize_kernel(float* __restrict__ out)
{
    __shared__ float llS[BB];
    __shared__ int   cS[BB];
    __shared__ int   tS[BB];
    int k = threadIdx.x;   // 256 threads
    llS[k] = g_ll[k]; cS[k] = g_correct[k]; tS[k] = g_total[k];
    __syncthreads();
    if (k == 0) {
        float s = 0.f; int c = 0, t = 0;
        for (int i = 0; i < BB; i++) { s += llS[i]; c += cS[i]; t += tS[i]; }
        out[0] = -s / (float)BB;
        out[1 + BB * TT] = (float)c / (float)t;
    }
}

extern "C" void kernel_launch(void* const* d_in, const int* in_sizes, int n_in,
                              void* d_out, int out_size)
{
    const float* emissions = (const float*)d_in[0];   // (256,512,128) f32
    const int*   tag_ids   = (const int*)d_in[1];     // (256,512) i32
    const int*   lengths   = (const int*)d_in[2];     // (256,) i32
    const float* trans     = (const float*)d_in[3];   // (128,128) f32
    float* out = (float*)d_out;                       // [loss, decoded(B*T), acc]

    crf_scan_kernel<<<2 * BB, 128>>>(emissions, lengths, trans);
    crf_backtrack_kernel<<<BB, 128>>>(emissions, tag_ids, lengths, trans, out);
    crf_finalize_kernel<<<1, BB>>>(out);
}

// round 4
// speedup vs baseline: 1.3014x; 1.3014x over previous
#include <cuda_runtime.h>

#define BB 256
#define TT 512
#define KK 128

// ---- scratch (no allocations allowed) ----
__device__ float g_v[(long)BB * TT * KK];   // 64MB: viterbi values per (b,t,k)
__device__ float g_transT[KK * KK];         // transT[c*K+j] = trans[j*K+c]
__device__ float g_lognorm[BB];
__device__ float g_ll[BB];
__device__ int   g_correct[BB];
__device__ int   g_total[BB];

// ============================================================
// Kernel 0: transpose transitions (tiny).
// ============================================================
__global__ void transpose_kernel(const float* __restrict__ trans)
{
    int c = blockIdx.x, j = threadIdx.x;
    g_transT[c * KK + j] = trans[j * KK + c];
}

// ============================================================
// Kernel 1: fused scans. Blocks [0,256) = Viterbi forward
// (VALUES ONLY, no backpointers), blocks [256,512) = CRF
// forward (exp-domain logsumexp). One thread per dest tag k.
// ============================================================
__global__ __launch_bounds__(128)
void crf_scan_kernel(const float* __restrict__ emissions,
                     const int*   __restrict__ lengths,
                     const float* __restrict__ trans)
{
    __shared__ float4 bufS[2][KK / 4];   // state vector (double buffer)
    __shared__ float  redS[4];

    const int k    = threadIdx.x;
    const int role = (blockIdx.x >= BB);
    const int b    = role ? (blockIdx.x - BB) : blockIdx.x;
    const int len  = lengths[b];
    const float* em = emissions + (long)b * TT * KK;

    if (!role) {
        // -------- Viterbi forward: max values only --------
        float tr[KK];
        #pragma unroll
        for (int j = 0; j < KK; j++) tr[j] = trans[j * KK + k];  // column k

        float* vglob = g_v + (long)b * TT * KK;

        float v = em[k];                       // t = 0
        vglob[k] = v;
        int buf = 0;
        ((float*)bufS[0])[k] = v;
        __syncthreads();

        float emit = em[KK + k];               // prefetch t = 1
        for (int t = 1; t < TT; t++) {
            float emit_next = (t + 1 < TT) ? em[(t + 1) * KK + k] : 0.0f;

            float b0 = -3.4e38f, b1 = -3.4e38f, b2 = -3.4e38f, b3 = -3.4e38f;
            #pragma unroll
            for (int jj = 0; jj < KK / 4; jj++) {
                float4 q = bufS[buf][jj];
                b0 = fmaxf(b0, q.x + tr[4*jj + 0]);
                b1 = fmaxf(b1, q.y + tr[4*jj + 1]);
                b2 = fmaxf(b2, q.z + tr[4*jj + 2]);
                b3 = fmaxf(b3, q.w + tr[4*jj + 3]);
            }
            float best = fmaxf(fmaxf(b0, b1), fmaxf(b2, b3));
            if (t < len) v = best + emit;
            vglob[t * KK + k] = v;

            ((float*)bufS[buf ^ 1])[k] = v;
            __syncthreads();
            buf ^= 1;
            emit = emit_next;
        }
    } else {
        // -------- CRF forward (log partition), exp-domain --------
        float Ereg[KK];
        #pragma unroll
        for (int j = 0; j < KK; j++) Ereg[j] = __expf(trans[j * KK + k]);

        float alpha = em[k];
        const int wid = k >> 5, lane = k & 31;

        float emit = em[KK + k];
        for (int t = 1; t < TT; t++) {
            float emit_next = (t + 1 < TT) ? em[(t + 1) * KK + k] : 0.0f;

            // block max of alpha
            float mw = alpha;
            #pragma unroll
            for (int o = 16; o > 0; o >>= 1)
                mw = fmaxf(mw, __shfl_xor_sync(0xffffffffu, mw, o));
            if (lane == 0) redS[wid] = mw;
            __syncthreads();
            float m = fmaxf(fmaxf(redS[0], redS[1]), fmaxf(redS[2], redS[3]));

            float p = __expf(alpha - m);
            ((float*)bufS[0])[k] = p;
            __syncthreads();

            float s0 = 0.f, s1 = 0.f, s2 = 0.f, s3 = 0.f;
            #pragma unroll
            for (int jj = 0; jj < KK / 4; jj++) {
                float4 q = bufS[0][jj];
                s0 = fmaf(q.x, Ereg[4*jj + 0], s0);
                s1 = fmaf(q.y, Ereg[4*jj + 1], s1);
                s2 = fmaf(q.z, Ereg[4*jj + 2], s2);
                s3 = fmaf(q.w, Ereg[4*jj + 3], s3);
            }
            float s = (s0 + s1) + (s2 + s3);
            if (t < len) alpha = m + __logf(s) + emit;
            emit = emit_next;
        }

        // final logsumexp over k
        float mw = alpha;
        #pragma unroll
        for (int o = 16; o > 0; o >>= 1)
            mw = fmaxf(mw, __shfl_xor_sync(0xffffffffu, mw, o));
        if (lane == 0) redS[wid] = mw;
        __syncthreads();
        float m = fmaxf(fmaxf(redS[0], redS[1]), fmaxf(redS[2], redS[3]));
        float p = __expf(alpha - m);
        #pragma unroll
        for (int o = 16; o > 0; o >>= 1)
            p += __shfl_xor_sync(0xffffffffu, p, o);
        __syncthreads();
        if (lane == 0) redS[wid] = p;
        __syncthreads();
        if (k == 0) {
            float s = redS[0] + redS[1] + redS[2] + redS[3];
            g_lognorm[b] = m + __logf(s);
        }
    }
}

// ============================================================
// Kernel 2: path backtrack by argmax recomputation along the
// surviving path only, + gold score + accuracy. 1 warp/batch.
// ============================================================
__global__ __launch_bounds__(32)
void crf_backward_kernel(const float* __restrict__ emissions,
                         const int*   __restrict__ tag_ids,
                         const int*   __restrict__ lengths,
                         float*       __restrict__ out)
{
    __shared__ int tagS[TT];

    const int b    = blockIdx.x;
    const int lane = threadIdx.x;
    const int len  = lengths[b];
    const float* vb = g_v + (long)b * TT * KK;

    // ---- last_tag = argmax(v_final), first index on ties ----
    float4 q = __ldg((const float4*)(vb + (TT - 1) * KK) + lane);
    float bv = q.x; int bi = 0;
    if (q.y > bv) { bv = q.y; bi = 1; }
    if (q.z > bv) { bv = q.z; bi = 2; }
    if (q.w > bv) { bv = q.w; bi = 3; }
    unsigned key = __float_as_uint(bv);
    key ^= ((unsigned)((int)key >> 31)) | 0x80000000u;   // ordered-uint map
    unsigned mk   = __reduce_max_sync(0xffffffffu, key);
    unsigned ball = __ballot_sync(0xffffffffu, key == mk);
    int src = __ffs(ball) - 1;
    int cur = (src << 2) + __shfl_sync(0xffffffffu, bi, src);
    if (lane == 0) tagS[TT - 1] = cur;

    // ---- backward walk: recompute argmax for the needed row only ----
    float4 pre0 = __ldcs((const float4*)(vb + (TT - 2) * KK) + lane);
    float4 pre1 = __ldcs((const float4*)(vb + (TT - 3) * KK) + lane);
    for (int t = TT - 1; t >= 1; t--) {
        float4 vrow = pre0;
        pre0 = pre1;
        int nr = t - 3; if (nr < 0) nr = 0;
        pre1 = __ldcs((const float4*)(vb + nr * KK) + lane);

        if (t < len) {
            float4 tc = __ldg((const float4*)(g_transT + (cur << 7)) + lane);
            float w0 = vrow.x + tc.x, w1 = vrow.y + tc.y;
            float w2 = vrow.z + tc.z, w3 = vrow.w + tc.w;
            float lb = w0; int li = 0;
            if (w1 > lb) { lb = w1; li = 1; }
            if (w2 > lb) { lb = w2; li = 2; }
            if (w3 > lb) { lb = w3; li = 3; }
            unsigned k2 = __float_as_uint(lb);
            k2 ^= ((unsigned)((int)k2 >> 31)) | 0x80000000u;
            unsigned m2 = __reduce_max_sync(0xffffffffu, k2);
            unsigned b2 = __ballot_sync(0xffffffffu, k2 == m2);
            int s2 = __ffs(b2) - 1;
            cur = (s2 << 2) + __shfl_sync(0xffffffffu, li, s2);
        }
        if (lane == 0) tagS[t - 1] = cur;
    }
    __syncwarp();

    // ---- decoded output + gold-path score + accuracy ----
    float sc = 0.f;
    int correct = 0;
    for (int t = lane; t < TT; t += 32) {
        int tg = tagS[t];
        out[1 + b * TT + t] = (float)tg;
        int ref = __ldg(tag_ids + b * TT + t);
        if (t < len) {
            correct += (ref == tg);
            sc += __ldg(emissions + ((long)b * TT + t) * KK + ref);
            if (t >= 1) {
                int prev = __ldg(tag_ids + b * TT + t - 1);
                sc += __ldg(g_transT + (ref << 7) + prev);   // trans[prev][ref]
            }
        }
    }
    #pragma unroll
    for (int o = 16; o > 0; o >>= 1) {
        sc      += __shfl_xor_sync(0xffffffffu, sc, o);
        correct += __shfl_xor_sync(0xffffffffu, correct, o);
    }
    if (lane == 0) {
        g_ll[b]      = sc - g_lognorm[b];
        g_correct[b] = correct;
        g_total[b]   = len;
    }
}

// ============================================================
// Kernel 3: finalize loss + accuracy (deterministic).
// ============================================================
__global__ void crf_finalize_kernel(float* __restrict__ out)
{
    __shared__ float llS[BB];
    __shared__ int   cS[BB];
    __shared__ int   tS[BB];
    int k = threadIdx.x;   // 256 threads
    llS[k] = g_ll[k]; cS[k] = g_correct[k]; tS[k] = g_total[k];
    __syncthreads();
    if (k == 0) {
        float s = 0.f; int c = 0, t = 0;
        for (int i = 0; i < BB; i++) { s += llS[i]; c += cS[i]; t += tS[i]; }
        out[0] = -s / (float)BB;
        out[1 + BB * TT] = (float)c / (float)t;
    }
}

extern "C" void kernel_launch(void* const* d_in, const int* in_sizes, int n_in,
                              void* d_out, int out_size)
{
    const float* emissions = (const float*)d_in[0];   // (256,512,128) f32
    const int*   tag_ids   = (const int*)d_in[1];     // (256,512) i32
    const int*   lengths   = (const int*)d_in[2];     // (256,) i32
    const float* trans     = (const float*)d_in[3];   // (128,128) f32
    float* out = (float*)d_out;                       // [loss, decoded(B*T), acc]

    transpose_kernel<<<KK, KK>>>(trans);
    crf_scan_kernel<<<2 * BB, 128>>>(emissions, lengths, trans);
    crf_backward_kernel<<<BB, 32>>>(emissions, tag_ids, lengths, out);
    crf_finalize_kernel<<<1, BB>>>(out);
}

// round 6
// speedup vs baseline: 2.0067x; 1.5419x over previous
#include <cuda_runtime.h>

#define BB 256
#define TT 512
#define KK 128

// ---- scratch (no allocations allowed) ----
__device__ float g_v[(long)BB * TT * KK];   // 64MB: viterbi values per (b,t,k)
__device__ float g_transT[KK * KK];         // transT[c*K+j] = trans[j*K+c]
__device__ int   g_order[BB];               // batches sorted by length desc
__device__ float g_lognorm[BB];
__device__ float g_ll[BB];
__device__ int   g_correct[BB];
__device__ int   g_total[BB];

// ---- packed f32x2 helpers (sm_103a) ----
__device__ __forceinline__ unsigned long long f2pack(float a, float b) {
    unsigned long long r;
    asm("mov.b64 %0, {%1,%2};" : "=l"(r) : "f"(a), "f"(b));
    return r;
}
__device__ __forceinline__ void f2unpack(unsigned long long v, float& a, float& b) {
    asm("mov.b64 {%0,%1}, %2;" : "=f"(a), "=f"(b) : "l"(v));
}
__device__ __forceinline__ unsigned long long f2add(unsigned long long a, unsigned long long b) {
    unsigned long long r;
    asm("add.rn.f32x2 %0, %1, %2;" : "=l"(r) : "l"(a), "l"(b));
    return r;
}
__device__ __forceinline__ unsigned long long f2fma(unsigned long long a, unsigned long long b,
                                                    unsigned long long c) {
    unsigned long long r;
    asm("fma.rn.f32x2 %0, %1, %2, %3;" : "=l"(r) : "l"(a), "l"(b), "l"(c));
    return r;
}

// ============================================================
// Kernel 0a: transpose transitions (tiny).
// ============================================================
__global__ void transpose_kernel(const float* __restrict__ trans)
{
    int c = blockIdx.x, j = threadIdx.x;
    g_transT[c * KK + j] = trans[j * KK + c];
}

// ============================================================
// Kernel 0b: rank-sort batches by length descending (LPT).
// Deterministic tie-break by batch index.
// ============================================================
__global__ void sort_kernel(const int* __restrict__ lengths)
{
    __shared__ int keys[BB];
    int b = threadIdx.x;
    int key = (lengths[b] << 8) | (BB - 1 - b);
    keys[b] = key;
    __syncthreads();
    int r = 0;
    #pragma unroll 8
    for (int j = 0; j < BB; j++) r += (keys[j] > key);
    g_order[r] = b;
}

// ============================================================
// Kernel 1: fused scans with EARLY EXIT at t = len.
// Blocks [0,256) = Viterbi forward (values only),
// blocks [256,512) = CRF forward (exp-domain logsumexp,
// per-warp-max rescale -> single __syncthreads per step).
// One thread per destination tag k. Batches picked via g_order.
// ============================================================
__global__ __launch_bounds__(128)
void crf_scan_kernel(const float* __restrict__ emissions,
                     const int*   __restrict__ lengths,
                     const float* __restrict__ trans)
{
    __shared__ ulonglong2 bufP[2][KK / 4];   // packed state vector (double buffer)
    __shared__ float      redS[2][4];

    const int k    = threadIdx.x;
    const int role = (blockIdx.x >= BB);
    const int b    = g_order[role ? (blockIdx.x - BB) : blockIdx.x];
    const int len  = lengths[b];
    const float* em = emissions + (long)b * TT * KK;
    const int wid = k >> 5, lane = k & 31;

    if (!role) {
        // -------- Viterbi forward: max values only, t < len --------
        unsigned long long trp[KK / 2];      // packed transition column k
        #pragma unroll
        for (int m = 0; m < KK / 2; m++)
            trp[m] = f2pack(trans[(2 * m) * KK + k], trans[(2 * m + 1) * KK + k]);

        float* vglob = g_v + (long)b * TT * KK;

        float v = em[k];                     // t = 0
        vglob[k] = v;
        int buf = 0;
        ((float*)bufP[0])[k] = v;
        __syncthreads();

        float emit = em[KK + k];             // prefetch t = 1 (TT >= 2 always)
        for (int t = 1; t < len; t++) {
            float emit_next = (t + 1 < TT) ? em[(t + 1) * KK + k] : 0.0f;

            float b0 = -3.4e38f, b1 = -3.4e38f, b2 = -3.4e38f, b3 = -3.4e38f;
            #pragma unroll
            for (int jj = 0; jj < KK / 4; jj++) {
                ulonglong2 q = bufP[buf][jj];
                float x0, x1, x2, x3;
                f2unpack(f2add(q.x, trp[2 * jj]),     x0, x1);
                f2unpack(f2add(q.y, trp[2 * jj + 1]), x2, x3);
                b0 = fmaxf(b0, x0); b1 = fmaxf(b1, x1);
                b2 = fmaxf(b2, x2); b3 = fmaxf(b3, x3);
            }
            v = fmaxf(fmaxf(b0, b1), fmaxf(b2, b3)) + emit;
            vglob[t * KK + k] = v;

            ((float*)bufP[buf ^ 1])[k] = v;
            __syncthreads();
            buf ^= 1;
            emit = emit_next;
        }
        // rows t >= len are never read by backward (argmax uses row len-1)
    } else {
        // -------- CRF forward (log partition), exp-domain, t < len --------
        unsigned long long Ep[KK / 2];       // packed exp(transition) column k
        #pragma unroll
        for (int m = 0; m < KK / 2; m++)
            Ep[m] = f2pack(__expf(trans[(2 * m) * KK + k]),
                           __expf(trans[(2 * m + 1) * KK + k]));

        float alpha = em[k];
        int buf = 1;                         // first write goes to nb = 0

        float emit = em[KK + k];
        for (int t = 1; t < len; t++) {
            float emit_next = (t + 1 < TT) ? em[(t + 1) * KK + k] : 0.0f;

            // per-warp max of alpha
            float mw = alpha;
            #pragma unroll
            for (int o = 16; o > 0; o >>= 1)
                mw = fmaxf(mw, __shfl_xor_sync(0xffffffffu, mw, o));

            int nb = buf ^ 1;
            float p = __expf(alpha - mw);
            ((float*)bufP[nb])[k] = p;
            if (lane == 0) redS[nb][wid] = mw;
            __syncthreads();

            float m0 = redS[nb][0], m1 = redS[nb][1];
            float m2 = redS[nb][2], m3 = redS[nb][3];
            float m = fmaxf(fmaxf(m0, m1), fmaxf(m2, m3));

            // grouped packed dot: group g = j in [32g, 32g+32), warp g's p's
            unsigned long long acc0 = f2pack(0.f, 0.f), acc1 = acc0,
                               acc2 = acc0, acc3 = acc0;
            #pragma unroll
            for (int jj = 0; jj < 8; jj++) {
                ulonglong2 q = bufP[nb][jj];
                acc0 = f2fma(q.x, Ep[2 * jj],     acc0);
                acc0 = f2fma(q.y, Ep[2 * jj + 1], acc0);
            }
            #pragma unroll
            for (int jj = 8; jj < 16; jj++) {
                ulonglong2 q = bufP[nb][jj];
                acc1 = f2fma(q.x, Ep[2 * jj],     acc1);
                acc1 = f2fma(q.y, Ep[2 * jj + 1], acc1);
            }
            #pragma unroll
            for (int jj = 16; jj < 24; jj++) {
                ulonglong2 q = bufP[nb][jj];
                acc2 = f2fma(q.x, Ep[2 * jj],     acc2);
                acc2 = f2fma(q.y, Ep[2 * jj + 1], acc2);
            }
            #pragma unroll
            for (int jj = 24; jj < 32; jj++) {
                ulonglong2 q = bufP[nb][jj];
                acc3 = f2fma(q.x, Ep[2 * jj],     acc3);
                acc3 = f2fma(q.y, Ep[2 * jj + 1], acc3);
            }
            float lo, hi, s;
            f2unpack(acc0, lo, hi); s = __expf(m0 - m) * (lo + hi);
            f2unpack(acc1, lo, hi); s = fmaf(__expf(m1 - m), lo + hi, s);
            f2unpack(acc2, lo, hi); s = fmaf(__expf(m2 - m), lo + hi, s);
            f2unpack(acc3, lo, hi); s = fmaf(__expf(m3 - m), lo + hi, s);

            alpha = m + __logf(s) + emit;
            buf = nb;
            emit = emit_next;
        }

        // final logsumexp over k
        __syncthreads();
        float mw = alpha;
        #pragma unroll
        for (int o = 16; o > 0; o >>= 1)
            mw = fmaxf(mw, __shfl_xor_sync(0xffffffffu, mw, o));
        if (lane == 0) redS[0][wid] = mw;
        __syncthreads();
        float m = fmaxf(fmaxf(redS[0][0], redS[0][1]), fmaxf(redS[0][2], redS[0][3]));
        float p = __expf(alpha - m);
        #pragma unroll
        for (int o = 16; o > 0; o >>= 1)
            p += __shfl_xor_sync(0xffffffffu, p, o);
        __syncthreads();
        if (lane == 0) redS[0][wid] = p;
        __syncthreads();
        if (k == 0) {
            float s = redS[0][0] + redS[0][1] + redS[0][2] + redS[0][3];
            g_lognorm[b] = m + __logf(s);
        }
    }
}

// ============================================================
// Kernel 2: path backtrack by argmax recomputation along the
// surviving path only, + gold score + accuracy. 1 warp/batch.
// Walk runs only t in [1, len); tail filled with last_tag.
// ============================================================
__global__ __launch_bounds__(32)
void crf_backward_kernel(const float* __restrict__ emissions,
                         const int*   __restrict__ tag_ids,
                         const int*   __restrict__ lengths,
                         float*       __restrict__ out)
{
    __shared__ int tagS[TT];

    const int b    = blockIdx.x;
    const int lane = threadIdx.x;
    const int len  = lengths[b];
    const int t0   = len - 1;
    const float* vb = g_v + (long)b * TT * KK;

    // ---- last_tag = argmax(v at row len-1), first index on ties ----
    float4 q = __ldg((const float4*)(vb + (long)t0 * KK) + lane);
    float bv = q.x; int bi = 0;
    if (q.y > bv) { bv = q.y; bi = 1; }
    if (q.z > bv) { bv = q.z; bi = 2; }
    if (q.w > bv) { bv = q.w; bi = 3; }
    unsigned key = __float_as_uint(bv);
    key ^= ((unsigned)((int)key >> 31)) | 0x80000000u;   // ordered-uint map
    unsigned mk   = __reduce_max_sync(0xffffffffu, key);
    unsigned ball = __ballot_sync(0xffffffffu, key == mk);
    int src = __ffs(ball) - 1;
    int cur = (src << 2) + __shfl_sync(0xffffffffu, bi, src);

    // fill tail [t0, TT) with last_tag (matches identity backpointers)
    for (int t = t0 + lane; t < TT; t += 32) tagS[t] = cur;

    // ---- backward walk over t in [1, len) ----
    int r0 = t0 - 1; if (r0 < 0) r0 = 0;
    int r1 = t0 - 2; if (r1 < 0) r1 = 0;
    float4 pre0 = __ldcs((const float4*)(vb + (long)r0 * KK) + lane);
    float4 pre1 = __ldcs((const float4*)(vb + (long)r1 * KK) + lane);
    for (int t = t0; t >= 1; t--) {
        float4 vrow = pre0;
        pre0 = pre1;
        int nr = t - 3; if (nr < 0) nr = 0;
        pre1 = __ldcs((const float4*)(vb + (long)nr * KK) + lane);

        float4 tc = __ldg((const float4*)(g_transT + (cur << 7)) + lane);
        float w0 = vrow.x + tc.x, w1 = vrow.y + tc.y;
        float w2 = vrow.z + tc.z, w3 = vrow.w + tc.w;
        float lb = w0; int li = 0;
        if (w1 > lb) { lb = w1; li = 1; }
        if (w2 > lb) { lb = w2; li = 2; }
        if (w3 > lb) { lb = w3; li = 3; }
        unsigned k2 = __float_as_uint(lb);
        k2 ^= ((unsigned)((int)k2 >> 31)) | 0x80000000u;
        unsigned m2 = __reduce_max_sync(0xffffffffu, k2);
        unsigned b2 = __ballot_sync(0xffffffffu, k2 == m2);
        int s2 = __ffs(b2) - 1;
        cur = (s2 << 2) + __shfl_sync(0xffffffffu, li, s2);
        if (lane == 0) tagS[t - 1] = cur;
    }
    __syncwarp();

    // ---- decoded output + gold-path score + accuracy ----
    float sc = 0.f;
    int correct = 0;
    for (int t = lane; t < TT; t += 32) {
        int tg = tagS[t];
        out[1 + b * TT + t] = (float)tg;
        int ref = __ldg(tag_ids + b * TT + t);
        if (t < len) {
            correct += (ref == tg);
            sc += __ldg(emissions + ((long)b * TT + t) * KK + ref);
            if (t >= 1) {
                int prev = __ldg(tag_ids + b * TT + t - 1);
                sc += __ldg(g_transT + (ref << 7) + prev);   // trans[prev][ref]
            }
        }
    }
    #pragma unroll
    for (int o = 16; o > 0; o >>= 1) {
        sc      += __shfl_xor_sync(0xffffffffu, sc, o);
        correct += __shfl_xor_sync(0xffffffffu, correct, o);
    }
    if (lane == 0) {
        g_ll[b]      = sc - g_lognorm[b];
        g_correct[b] = correct;
        g_total[b]   = len;
    }
}

// ============================================================
// Kernel 3: finalize loss + accuracy (deterministic).
// ============================================================
__global__ void crf_finalize_kernel(float* __restrict__ out)
{
    __shared__ float llS[BB];
    __shared__ int   cS[BB];
    __shared__ int   tS[BB];
    int k = threadIdx.x;   // 256 threads
    llS[k] = g_ll[k]; cS[k] = g_correct[k]; tS[k] = g_total[k];
    __syncthreads();
    if (k == 0) {
        float s = 0.f; int c = 0, t = 0;
        for (int i = 0; i < BB; i++) { s += llS[i]; c += cS[i]; t += tS[i]; }
        out[0] = -s / (float)BB;
        out[1 + BB * TT] = (float)c / (float)t;
    }
}

extern "C" void kernel_launch(void* const* d_in, const int* in_sizes, int n_in,
                              void* d_out, int out_size)
{
    const float* emissions = (const float*)d_in[0];   // (256,512,128) f32
    const int*   tag_ids   = (const int*)d_in[1];     // (256,512) i32
    const int*   lengths   = (const int*)d_in[2];     // (256,) i32
    const float* trans     = (const float*)d_in[3];   // (128,128) f32
    float* out = (float*)d_out;                       // [loss, decoded(B*T), acc]

    sort_kernel<<<1, BB>>>(lengths);
    transpose_kernel<<<KK, KK>>>(trans);
    crf_scan_kernel<<<2 * BB, 128>>>(emissions, lengths, trans);
    crf_backward_kernel<<<BB, 32>>>(emissions, tag_ids, lengths, out);
    crf_finalize_kernel<<<1, BB>>>(out);
}